// round 15
// baseline (speedup 1.0000x reference)
#include <cuda_runtime.h>
#include <cuda_fp16.h>
#include <cstdint>
#include <cstddef>

#define B_   4
#define T_   2048
#define C_   1024
#define H_   16
#define MTOK 8192
// Q scale folded with log2(e) for exp2-domain softmax
#define QSCALE 0.18033688011112042f

// ---------------------------------------------------------------------------
// Scratch
// ---------------------------------------------------------------------------
__device__ __half g_xh[(size_t)MTOK * C_],     g_xl[(size_t)MTOK * C_];
__device__ __half g_wqh[(size_t)3 * C_ * C_],  g_wql[(size_t)3 * C_ * C_];
__device__ __half g_woh[(size_t)C_ * C_],      g_wol[(size_t)C_ * C_];
__device__ __half g_qh[(size_t)MTOK * 3 * C_], g_ql[(size_t)MTOK * 3 * C_];
__device__ __half g_ch[(size_t)MTOK * C_];
__device__ float  g_attn[(size_t)MTOK * C_];

// ---------------------------------------------------------------------------
// Helpers
// ---------------------------------------------------------------------------
__device__ __forceinline__ uint32_t su32(const void* p) {
    uint32_t a;
    asm("{ .reg .u64 t; cvta.to.shared.u64 t, %1; cvt.u32.u64 %0, t; }"
        : "=r"(a) : "l"(p));
    return a;
}
__device__ __forceinline__ void cpa16(uint32_t dst, const void* src) {
    asm volatile("cp.async.cg.shared.global [%0], [%1], 16;" :: "r"(dst), "l"(src));
}
#define CP_COMMIT() asm volatile("cp.async.commit_group;" ::: "memory")

__device__ __forceinline__ void ldm4(uint32_t* r, uint32_t a) {
    asm volatile("ldmatrix.sync.aligned.m8n8.x4.shared.b16 {%0,%1,%2,%3}, [%4];"
                 : "=r"(r[0]), "=r"(r[1]), "=r"(r[2]), "=r"(r[3]) : "r"(a));
}
__device__ __forceinline__ void ldm4t(uint32_t* r, uint32_t a) {
    asm volatile("ldmatrix.sync.aligned.m8n8.x4.trans.shared.b16 {%0,%1,%2,%3}, [%4];"
                 : "=r"(r[0]), "=r"(r[1]), "=r"(r[2]), "=r"(r[3]) : "r"(a));
}
__device__ __forceinline__ void mma16(float* d, const uint32_t* a, const uint32_t* b) {
    asm volatile(
        "mma.sync.aligned.m16n8k16.row.col.f32.f16.f16.f32 "
        "{%0,%1,%2,%3}, {%4,%5,%6,%7}, {%8,%9}, {%0,%1,%2,%3};"
        : "+f"(d[0]), "+f"(d[1]), "+f"(d[2]), "+f"(d[3])
        : "r"(a[0]), "r"(a[1]), "r"(a[2]), "r"(a[3]), "r"(b[0]), "r"(b[1]));
}
__device__ __forceinline__ void split2(float x, float y, uint32_t& h, uint32_t& l) {
    __half2 hh = __float22half2_rn(make_float2(x, y));
    float rx = x - __half2float(__low2half(hh));
    float ry = y - __half2float(__high2half(hh));
    __half2 ll = __float22half2_rn(make_float2(rx, ry));
    h = *reinterpret_cast<uint32_t*>(&hh);
    l = *reinterpret_cast<uint32_t*>(&ll);
}
__device__ __forceinline__ uint32_t pack_h2(float x, float y) {
    __half2 hh = __float22half2_rn(make_float2(x, y));
    return *reinterpret_cast<uint32_t*>(&hh);
}

// ---------------------------------------------------------------------------
// fp32 -> fp16 hi/lo split
// ---------------------------------------------------------------------------
__global__ void __launch_bounds__(256)
split_pair(const float2* __restrict__ in, __half2* __restrict__ oh,
           __half2* __restrict__ ol, int n2)
{
    int i = blockIdx.x * blockDim.x + threadIdx.x;
    if (i >= n2) return;
    float2 v = in[i];
    uint32_t h, l;
    split2(v.x, v.y, h, l);
    oh[i] = *reinterpret_cast<__half2*>(&h);
    ol[i] = *reinterpret_cast<__half2*>(&l);
}

// ---------------------------------------------------------------------------
// fp16-compensated GEMM (NT): 128x128 tile, BK=32, 3-stage pipeline,
// one __syncthreads per chunk, 2 CTAs/SM. NPASS=3: hh+hl+lh; NPASS=2: hh+hl.
// ---------------------------------------------------------------------------
#define GSM 98304

template<int NOUT, bool SPLIT, int NPASS, bool QS>
__global__ void __launch_bounds__(256, 2)
gemm16(const __half* __restrict__ Ah, const __half* __restrict__ Al,
       const __half* __restrict__ Bh, const __half* __restrict__ Bl,
       float* __restrict__ outF, __half* __restrict__ outH,
       __half* __restrict__ outL)
{
    extern __shared__ char smx[];
    const uint32_t smB = su32(smx);
    const int tid  = threadIdx.x;
    const int lane = tid & 31;
    const int wid  = tid >> 5;
    const int wm   = wid & 1;
    const int wn   = wid >> 1;
    const int lr   = lane & 7, g = lane >> 3;
    const int qr   = lane >> 2, qc = lane & 3;
    const int bm   = blockIdx.y * 128;
    const int bn   = blockIdx.x * 128;

    const int aCh = g >> 1;
    const int bCh = g & 1;
    const int aRowF = lr + ((g & 1) << 3);
    const int bRowF = lr + ((g >> 1) << 3);

    const int id0 = tid * 2, id1 = tid * 2 + 1;
    const int r0 = id0 >> 2, c0 = id0 & 3;
    const int r1 = id1 >> 2, c1 = id1 & 3;
    const uint32_t o0 = r0 * 64 + (((c0 ^ ((r0 >> 1) & 3))) << 4);
    const uint32_t o1 = r1 * 64 + (((c1 ^ ((r1 >> 1) & 3))) << 4);

    auto stage = [&](int k0, int s) {
        const uint32_t bb = smB + s * 32768;
        const size_t a0 = (size_t)(bm + r0) * 1024 + k0 + c0 * 8;
        const size_t a1 = (size_t)(bm + r1) * 1024 + k0 + c1 * 8;
        const size_t b0 = (size_t)(bn + r0) * 1024 + k0 + c0 * 8;
        const size_t b1 = (size_t)(bn + r1) * 1024 + k0 + c1 * 8;
        cpa16(bb + o0,         Ah + a0);  cpa16(bb + o1,         Ah + a1);
        if (NPASS == 3) {
            cpa16(bb + 8192 + o0, Al + a0);
            cpa16(bb + 8192 + o1, Al + a1);
        }
        cpa16(bb + 16384 + o0, Bh + b0);  cpa16(bb + 16384 + o1, Bh + b1);
        cpa16(bb + 24576 + o0, Bl + b0);  cpa16(bb + 24576 + o1, Bl + b1);
        CP_COMMIT();
    };

    float c[4][4][4];
#pragma unroll
    for (int i = 0; i < 4; i++)
#pragma unroll
        for (int j = 0; j < 4; j++)
#pragma unroll
            for (int e = 0; e < 4; e++) c[i][j][e] = 0.f;

    stage(0, 0);
    stage(32, 1);

    for (int ki = 0; ki < 32; ki++) {
        if (ki < 31) asm volatile("cp.async.wait_group 1;" ::: "memory");
        else         asm volatile("cp.async.wait_group 0;" ::: "memory");
        __syncthreads();
        if (ki + 2 < 32) stage((ki + 2) * 32, (ki + 2) % 3);

        const uint32_t st = smB + (ki % 3) * 32768;

#pragma unroll
        for (int kk = 0; kk < 2; kk++) {
            uint32_t af[4][4];
#pragma unroll
            for (int i = 0; i < 4; i++) {
                const int row = wm * 64 + i * 16 + aRowF;
                ldm4(af[i], st + row * 64 +
                     (((2 * kk + aCh) ^ ((row >> 1) & 3)) << 4));
            }
            uint32_t bh4[2][4], bl4[2][4];
#pragma unroll
            for (int jp = 0; jp < 2; jp++) {
                const int row = wn * 32 + jp * 16 + bRowF;
                const uint32_t a = st + 16384 + row * 64 +
                                   (((2 * kk + bCh) ^ ((row >> 1) & 3)) << 4);
                ldm4(bh4[jp], a);
                ldm4(bl4[jp], a + 8192);
            }
#pragma unroll
            for (int jp = 0; jp < 2; jp++)
#pragma unroll
                for (int i = 0; i < 4; i++) {
                    mma16(c[i][2 * jp],     af[i], bh4[jp]);
                    mma16(c[i][2 * jp + 1], af[i], bh4[jp] + 2);
                }
#pragma unroll
            for (int jp = 0; jp < 2; jp++)
#pragma unroll
                for (int i = 0; i < 4; i++) {
                    mma16(c[i][2 * jp],     af[i], bl4[jp]);
                    mma16(c[i][2 * jp + 1], af[i], bl4[jp] + 2);
                }
            if (NPASS == 3) {
#pragma unroll
                for (int i = 0; i < 4; i++) {
                    const int row = wm * 64 + i * 16 + aRowF;
                    ldm4(af[i], st + 8192 + row * 64 +
                         (((2 * kk + aCh) ^ ((row >> 1) & 3)) << 4));
                }
#pragma unroll
                for (int jp = 0; jp < 2; jp++)
#pragma unroll
                    for (int i = 0; i < 4; i++) {
                        mma16(c[i][2 * jp],     af[i], bh4[jp]);
                        mma16(c[i][2 * jp + 1], af[i], bh4[jp] + 2);
                    }
            }
        }
    }

#pragma unroll
    for (int i = 0; i < 4; i++) {
#pragma unroll
        for (int j = 0; j < 4; j++) {
            const int row = bm + wm * 64 + i * 16 + qr;
            const int col = bn + wn * 32 + j * 8 + 2 * qc;
            if (SPLIT) {
                const float sc = (QS && col < 1024) ? QSCALE : 1.f;
                uint32_t h0, l0, h1, l1;
                split2(c[i][j][0] * sc, c[i][j][1] * sc, h0, l0);
                split2(c[i][j][2] * sc, c[i][j][3] * sc, h1, l1);
                *(uint32_t*)(outH + (size_t)row * NOUT + col) = h0;
                *(uint32_t*)(outL + (size_t)row * NOUT + col) = l0;
                *(uint32_t*)(outH + (size_t)(row + 8) * NOUT + col) = h1;
                *(uint32_t*)(outL + (size_t)(row + 8) * NOUT + col) = l1;
            } else {
                *(float2*)(outF + (size_t)row * NOUT + col) =
                    make_float2(c[i][j][0], c[i][j][1]);
                *(float2*)(outF + (size_t)(row + 8) * NOUT + col) =
                    make_float2(c[i][j][2], c[i][j][3]);
            }
        }
    }
}

// ---------------------------------------------------------------------------
// Flash attention (causal) v5: LPT scheduling — bh on blockIdx.x (fast),
// q-tile on blockIdx.y REVERSED so largest-work CTAs launch first.
// 3-stage KV pipeline, one barrier/tile, S 3-pass, PV = Ph*Vh, exp2 softmax.
// ---------------------------------------------------------------------------
#define FA_SMEM 73728

__global__ void __launch_bounds__(128, 3)
flash16(const __half* __restrict__ qh, const __half* __restrict__ ql,
        float* __restrict__ out)
{
    extern __shared__ char smx[];
    const uint32_t smB = su32(smx);
    const int tid  = threadIdx.x;
    const int w    = tid >> 5;
    const int lane = tid & 31;
    const int lr   = lane & 7, g = lane >> 3;
    const int qr   = lane >> 2, qc = lane & 3;
    const int bhx  = blockIdx.x;                       // bh on fast axis
    const int b    = bhx >> 4;
    const int hh   = bhx & 15;
    const int m0   = (gridDim.y - 1 - blockIdx.y) * 64; // largest first (LPT)
    const int nt   = m0 / 64 + 1;

    const size_t base = (size_t)b * T_ * 3072 + hh * 64;
    const __half* qhp = qh + base;
    const __half* qlp = ql + base;
    const __half* khp = qhp + 1024;
    const __half* klp = qlp + 1024;
    const __half* vhp = qhp + 2048;

    int sRow[4], sC[4];
    uint32_t sDst[4];
#pragma unroll
    for (int q = 0; q < 4; q++) {
        int id = tid * 4 + q;
        sRow[q] = id >> 3;
        sC[q]   = id & 7;
        sDst[q] = sRow[q] * 128 + ((sC[q] ^ (sRow[q] & 7)) << 4);
    }

    auto stage_kv = [&](int t, int s) {
        const uint32_t bb = smB + s * 24576;
        const int j0 = t * 64;
#pragma unroll
        for (int q = 0; q < 4; q++) {
            const size_t so = (size_t)(j0 + sRow[q]) * 3072 + sC[q] * 8;
            cpa16(bb + sDst[q],         khp + so);
            cpa16(bb + 8192  + sDst[q], klp + so);
            cpa16(bb + 16384 + sDst[q], vhp + so);
        }
        CP_COMMIT();
    };

#pragma unroll
    for (int q = 0; q < 4; q++) {
        const size_t so = (size_t)(m0 + sRow[q]) * 3072 + sC[q] * 8;
        cpa16(smB + sDst[q],        qhp + so);
        cpa16(smB + 8192 + sDst[q], qlp + so);
    }
    CP_COMMIT();
    asm volatile("cp.async.wait_group 0;" ::: "memory");
    __syncthreads();

    const int aRow = lr + ((g & 1) << 3), aCh = g >> 1;
    const int kRow = lr + ((g >> 1) << 3), kCh = g & 1;
    uint32_t qfh[4][4], qfl[4][4];
#pragma unroll
    for (int kk = 0; kk < 4; kk++) {
        uint32_t a = smB + (w * 16 + aRow) * 128 + (((2 * kk + aCh) ^ lr) << 4);
        ldm4(qfh[kk], a);
        ldm4(qfl[kk], a + 8192);
    }
    __syncthreads();

    stage_kv(0, 0);
    if (nt > 1) stage_kv(1, 1);

    float o_[8][4];
#pragma unroll
    for (int n = 0; n < 8; n++)
#pragma unroll
        for (int e = 0; e < 4; e++) o_[n][e] = 0.f;
    float m0v = -1e30f, m1v = -1e30f, l0v = 0.f, l1v = 0.f;
    const int row0 = m0 + w * 16 + qr;

    for (int t = 0; t < nt; t++) {
        const int j0 = t * 64;
        if (t + 1 < nt) asm volatile("cp.async.wait_group 1;" ::: "memory");
        else            asm volatile("cp.async.wait_group 0;" ::: "memory");
        __syncthreads();
        if (t + 2 < nt) stage_kv(t + 2, (t + 2) % 3);

        const uint32_t KB = smB + (t % 3) * 24576;
        const uint32_t VB = KB + 16384;

        float s_[8][4];
#pragma unroll
        for (int n = 0; n < 8; n++)
#pragma unroll
            for (int e = 0; e < 4; e++) s_[n][e] = 0.f;

#pragma unroll
        for (int kk = 0; kk < 4; kk++) {
            uint32_t kh4[4][4], kl4[4][4];
#pragma unroll
            for (int np = 0; np < 4; np++) {
                uint32_t a = KB + np * 2048 + kRow * 128 +
                             (((2 * kk + kCh) ^ lr) << 4);
                ldm4(kh4[np], a);
                ldm4(kl4[np], a + 8192);
            }
#pragma unroll
            for (int np = 0; np < 4; np++) {
                mma16(s_[2 * np],     qfh[kk], kh4[np]);
                mma16(s_[2 * np + 1], qfh[kk], kh4[np] + 2);
            }
#pragma unroll
            for (int np = 0; np < 4; np++) {
                mma16(s_[2 * np],     qfh[kk], kl4[np]);
                mma16(s_[2 * np + 1], qfh[kk], kl4[np] + 2);
            }
#pragma unroll
            for (int np = 0; np < 4; np++) {
                mma16(s_[2 * np],     qfl[kk], kh4[np]);
                mma16(s_[2 * np + 1], qfl[kk], kh4[np] + 2);
            }
        }

        if (j0 == m0) {
#pragma unroll
            for (int n = 0; n < 8; n++) {
                const int key = j0 + n * 8 + 2 * qc;
                if (key     > row0)     s_[n][0] = -1e30f;
                if (key + 1 > row0)     s_[n][1] = -1e30f;
                if (key     > row0 + 8) s_[n][2] = -1e30f;
                if (key + 1 > row0 + 8) s_[n][3] = -1e30f;
            }
        }

        float mx0 = -1e30f, mx1 = -1e30f;
#pragma unroll
        for (int n = 0; n < 8; n++) {
            mx0 = fmaxf(mx0, fmaxf(s_[n][0], s_[n][1]));
            mx1 = fmaxf(mx1, fmaxf(s_[n][2], s_[n][3]));
        }
        mx0 = fmaxf(mx0, __shfl_xor_sync(0xffffffffu, mx0, 1));
        mx0 = fmaxf(mx0, __shfl_xor_sync(0xffffffffu, mx0, 2));
        mx1 = fmaxf(mx1, __shfl_xor_sync(0xffffffffu, mx1, 1));
        mx1 = fmaxf(mx1, __shfl_xor_sync(0xffffffffu, mx1, 2));
        const float mn0 = fmaxf(m0v, mx0);
        const float mn1 = fmaxf(m1v, mx1);
        const float c0 = exp2f(m0v - mn0);
        const float c1 = exp2f(m1v - mn1);
        m0v = mn0; m1v = mn1;
        l0v *= c0;  l1v *= c1;
#pragma unroll
        for (int n = 0; n < 8; n++) {
            o_[n][0] *= c0; o_[n][1] *= c0;
            o_[n][2] *= c1; o_[n][3] *= c1;
        }

        uint32_t pA[8], pB[8];
        float ps0 = 0.f, ps1 = 0.f;
#pragma unroll
        for (int n = 0; n < 8; n++) {
            float p0 = exp2f(s_[n][0] - mn0);
            float p1 = exp2f(s_[n][1] - mn0);
            float p2 = exp2f(s_[n][2] - mn1);
            float p3 = exp2f(s_[n][3] - mn1);
            ps0 += p0 + p1;
            ps1 += p2 + p3;
            pA[n] = pack_h2(p0, p1);
            pB[n] = pack_h2(p2, p3);
        }
        ps0 += __shfl_xor_sync(0xffffffffu, ps0, 1);
        ps0 += __shfl_xor_sync(0xffffffffu, ps0, 2);
        ps1 += __shfl_xor_sync(0xffffffffu, ps1, 1);
        ps1 += __shfl_xor_sync(0xffffffffu, ps1, 2);
        l0v += ps0; l1v += ps1;

#pragma unroll
        for (int kk = 0; kk < 4; kk++) {
            uint32_t ah4[4] = { pA[2 * kk], pB[2 * kk],
                                pA[2 * kk + 1], pB[2 * kk + 1] };
#pragma unroll
            for (int np = 0; np < 4; np++) {
                uint32_t vh4[4];
                uint32_t a = VB + kk * 2048 + aRow * 128 +
                             (((2 * np + aCh) ^ lr) << 4);
                ldm4t(vh4, a);
                mma16(o_[2 * np],     ah4, vh4);
                mma16(o_[2 * np + 1], ah4, vh4 + 2);
            }
        }
    }

    const float i0 = 1.f / l0v;
    const float i1 = 1.f / l1v;
    float* oP0 = out + ((size_t)b * T_ + row0) * C_ + hh * 64;
    float* oP1 = oP0 + 8 * C_;
#pragma unroll
    for (int n = 0; n < 8; n++) {
        *(float2*)(oP0 + n * 8 + 2 * qc) = make_float2(o_[n][0] * i0, o_[n][1] * i0);
        *(float2*)(oP1 + n * 8 + 2 * qc) = make_float2(o_[n][2] * i1, o_[n][3] * i1);
    }
}

// ---------------------------------------------------------------------------
// Depthwise causal conv (K=4) + bias + residual -> fp16 hi only
// ---------------------------------------------------------------------------
__global__ void __launch_bounds__(256)
conv_h(const float* __restrict__ x, const float* __restrict__ w,
       const float* __restrict__ bias, __half* __restrict__ yh)
{
    int i2 = blockIdx.x * blockDim.x + threadIdx.x;
    if (i2 >= MTOK * C_ / 2) return;
    const int idx = i2 * 2;
    const int c = idx & (C_ - 1);
    const int t = (idx >> 10) & (T_ - 1);

    float s0 = bias[c]     + x[idx];
    float s1 = bias[c + 1] + x[idx + 1];
#pragma unroll
    for (int k = 0; k < 4; k++) {
        int ts = t + k - 3;
        if (ts >= 0) {
            s0 += w[c * 4 + k]       * x[idx + (k - 3) * C_];
            s1 += w[(c + 1) * 4 + k] * x[idx + 1 + (k - 3) * C_];
        }
    }
    *(uint32_t*)(yh + idx) = pack_h2(s0, s1);
}

// ---------------------------------------------------------------------------
// Launch
// ---------------------------------------------------------------------------
extern "C" void kernel_launch(void* const* d_in, const int* in_sizes, int n_in,
                              void* d_out, int out_size)
{
    const float* x     = (const float*)d_in[0];
    const float* Wqkv  = (const float*)d_in[1];
    const float* Wout  = (const float*)d_in[2];
    const float* convw = (const float*)d_in[3];
    const float* convb = (const float*)d_in[4];
    float* out = (float*)d_out;

    __half *xh, *xl, *wqh, *wql, *woh, *wol, *qh, *ql, *ch;
    float* attn;
    cudaGetSymbolAddress((void**)&xh,  g_xh);
    cudaGetSymbolAddress((void**)&xl,  g_xl);
    cudaGetSymbolAddress((void**)&wqh, g_wqh);
    cudaGetSymbolAddress((void**)&wql, g_wql);
    cudaGetSymbolAddress((void**)&woh, g_woh);
    cudaGetSymbolAddress((void**)&wol, g_wol);
    cudaGetSymbolAddress((void**)&qh,  g_qh);
    cudaGetSymbolAddress((void**)&ql,  g_ql);
    cudaGetSymbolAddress((void**)&ch,  g_ch);
    cudaGetSymbolAddress((void**)&attn, g_attn);

    cudaFuncSetAttribute((const void*)gemm16<3072, true, 3, true>,
                         cudaFuncAttributeMaxDynamicSharedMemorySize, GSM);
    cudaFuncSetAttribute((const void*)gemm16<3072, true, 2, false>,
                         cudaFuncAttributeMaxDynamicSharedMemorySize, GSM);
    cudaFuncSetAttribute((const void*)gemm16<1024, false, 2, false>,
                         cudaFuncAttributeMaxDynamicSharedMemorySize, GSM);
    cudaFuncSetAttribute((const void*)flash16,
                         cudaFuncAttributeMaxDynamicSharedMemorySize, FA_SMEM);

    // 0) split inputs
    split_pair<<<MTOK * C_ / 2 / 256, 256>>>((const float2*)x,
                                             (__half2*)xh, (__half2*)xl,
                                             MTOK * C_ / 2);
    split_pair<<<3 * C_ * C_ / 2 / 256, 256>>>((const float2*)Wqkv,
                                               (__half2*)wqh, (__half2*)wql,
                                               3 * C_ * C_ / 2);
    split_pair<<<C_ * C_ / 2 / 256, 256>>>((const float2*)Wout,
                                           (__half2*)woh, (__half2*)wol,
                                           C_ * C_ / 2);

    // 1a) Q+K projection (cols 0..2047): 3-pass, Q cols pre-scaled
    gemm16<3072, true, 3, true><<<dim3(16, 64), 256, GSM>>>(
        xh, xl, wqh, wql, nullptr, qh, ql);

    // 1b) V projection (cols 2048..3071): 2-pass
    gemm16<3072, true, 2, false><<<dim3(8, 64), 256, GSM>>>(
        xh, xl, wqh + (size_t)2048 * 1024, wql + (size_t)2048 * 1024,
        nullptr, qh + 2048, ql + 2048);

    // 2) attention — LPT grid: bh fast, q-tile reversed on y
    flash16<<<dim3(B_ * H_, T_ / 64), 128, FA_SMEM>>>(qh, ql, attn);

    // 3) conv + residual -> fp16 hi
    conv_h<<<MTOK * C_ / 2 / 256, 256>>>(attn, convw, convb, ch);

    // 4) output projection: 2-pass
    gemm16<1024, false, 2, false><<<dim3(8, 64), 256, GSM>>>(
        ch, nullptr, woh, wol, out, nullptr, nullptr);
}

// round 16
// speedup vs baseline: 1.0193x; 1.0193x over previous
#include <cuda_runtime.h>
#include <cuda_fp16.h>
#include <cstdint>
#include <cstddef>

#define B_   4
#define T_   2048
#define C_   1024
#define H_   16
#define MTOK 8192
// Q scale folded with log2(e) for exp2-domain softmax
#define QSCALE 0.18033688011112042f

// ---------------------------------------------------------------------------
// Scratch
// ---------------------------------------------------------------------------
__device__ __half g_xh[(size_t)MTOK * C_],     g_xl[(size_t)MTOK * C_];
__device__ __half g_wqh[(size_t)3 * C_ * C_],  g_wql[(size_t)3 * C_ * C_];
__device__ __half g_woh[(size_t)C_ * C_],      g_wol[(size_t)C_ * C_];
__device__ __half g_qh[(size_t)MTOK * 3 * C_], g_ql[(size_t)MTOK * 3 * C_];
__device__ __half g_ch[(size_t)MTOK * C_];
__device__ float  g_attn[(size_t)MTOK * C_];

// ---------------------------------------------------------------------------
// Helpers
// ---------------------------------------------------------------------------
__device__ __forceinline__ uint32_t su32(const void* p) {
    uint32_t a;
    asm("{ .reg .u64 t; cvta.to.shared.u64 t, %1; cvt.u32.u64 %0, t; }"
        : "=r"(a) : "l"(p));
    return a;
}
__device__ __forceinline__ void cpa16(uint32_t dst, const void* src) {
    asm volatile("cp.async.cg.shared.global [%0], [%1], 16;" :: "r"(dst), "l"(src));
}
#define CP_COMMIT() asm volatile("cp.async.commit_group;" ::: "memory")

__device__ __forceinline__ void ldm4(uint32_t* r, uint32_t a) {
    asm volatile("ldmatrix.sync.aligned.m8n8.x4.shared.b16 {%0,%1,%2,%3}, [%4];"
                 : "=r"(r[0]), "=r"(r[1]), "=r"(r[2]), "=r"(r[3]) : "r"(a));
}
__device__ __forceinline__ void ldm4t(uint32_t* r, uint32_t a) {
    asm volatile("ldmatrix.sync.aligned.m8n8.x4.trans.shared.b16 {%0,%1,%2,%3}, [%4];"
                 : "=r"(r[0]), "=r"(r[1]), "=r"(r[2]), "=r"(r[3]) : "r"(a));
}
__device__ __forceinline__ void mma16(float* d, const uint32_t* a, const uint32_t* b) {
    asm volatile(
        "mma.sync.aligned.m16n8k16.row.col.f32.f16.f16.f32 "
        "{%0,%1,%2,%3}, {%4,%5,%6,%7}, {%8,%9}, {%0,%1,%2,%3};"
        : "+f"(d[0]), "+f"(d[1]), "+f"(d[2]), "+f"(d[3])
        : "r"(a[0]), "r"(a[1]), "r"(a[2]), "r"(a[3]), "r"(b[0]), "r"(b[1]));
}
__device__ __forceinline__ void split2(float x, float y, uint32_t& h, uint32_t& l) {
    __half2 hh = __float22half2_rn(make_float2(x, y));
    float rx = x - __half2float(__low2half(hh));
    float ry = y - __half2float(__high2half(hh));
    __half2 ll = __float22half2_rn(make_float2(rx, ry));
    h = *reinterpret_cast<uint32_t*>(&hh);
    l = *reinterpret_cast<uint32_t*>(&ll);
}
__device__ __forceinline__ uint32_t pack_h2(float x, float y) {
    __half2 hh = __float22half2_rn(make_float2(x, y));
    return *reinterpret_cast<uint32_t*>(&hh);
}

// ---------------------------------------------------------------------------
// Fused fp32 -> fp16 hi/lo split for x (4M f), Wqkv (1.5M f2), Wout (0.5M f2)
// One launch over the concatenated index space.
// ---------------------------------------------------------------------------
#define X2  (MTOK * C_ / 2)
#define WQ2 (3 * C_ * C_ / 2)
#define WO2 (C_ * C_ / 2)

__global__ void __launch_bounds__(256)
split_all(const float2* __restrict__ x, const float2* __restrict__ wq,
          const float2* __restrict__ wo,
          __half2* __restrict__ xh, __half2* __restrict__ xl,
          __half2* __restrict__ wqh, __half2* __restrict__ wql,
          __half2* __restrict__ woh, __half2* __restrict__ wol)
{
    int i = blockIdx.x * blockDim.x + threadIdx.x;
    const float2* src;
    __half2 *dh, *dl;
    if (i < X2)                  { src = x  + i;               dh = xh  + i;               dl = xl  + i; }
    else if (i < X2 + WQ2)       { src = wq + (i - X2);        dh = wqh + (i - X2);        dl = wql + (i - X2); }
    else if (i < X2 + WQ2 + WO2) { src = wo + (i - X2 - WQ2);  dh = woh + (i - X2 - WQ2);  dl = wol + (i - X2 - WQ2); }
    else return;
    float2 v = *src;
    uint32_t h, l;
    split2(v.x, v.y, h, l);
    *dh = *reinterpret_cast<__half2*>(&h);
    *dl = *reinterpret_cast<__half2*>(&l);
}

// ---------------------------------------------------------------------------
// fp16-compensated GEMM (NT): 128x128 tile, BK=32, 3-stage pipeline,
// one __syncthreads per chunk, 2 CTAs/SM.
// NPASS=3: hh+hl+lh.  NPASS=2: hh+hl.
// NPASS=0 (MIXED, QKV): bn<2048 -> 3-pass (+QSCALE on cols<1024), else 2-pass.
// ---------------------------------------------------------------------------
#define GSM 98304

template<int NOUT, bool SPLIT, int NPASS, bool QS>
__global__ void __launch_bounds__(256, 2)
gemm16(const __half* __restrict__ Ah, const __half* __restrict__ Al,
       const __half* __restrict__ Bh, const __half* __restrict__ Bl,
       float* __restrict__ outF, __half* __restrict__ outH,
       __half* __restrict__ outL)
{
    extern __shared__ char smx[];
    const uint32_t smB = su32(smx);
    const int tid  = threadIdx.x;
    const int lane = tid & 31;
    const int wid  = tid >> 5;
    const int wm   = wid & 1;
    const int wn   = wid >> 1;
    const int lr   = lane & 7, g = lane >> 3;
    const int qr   = lane >> 2, qc = lane & 3;
    const int bm   = blockIdx.y * 128;
    const int bn   = blockIdx.x * 128;

    const bool p3 = (NPASS == 3) || (NPASS == 0 && bn < 2048);

    const int aCh = g >> 1;
    const int bCh = g & 1;
    const int aRowF = lr + ((g & 1) << 3);
    const int bRowF = lr + ((g >> 1) << 3);

    const int id0 = tid * 2, id1 = tid * 2 + 1;
    const int r0 = id0 >> 2, c0 = id0 & 3;
    const int r1 = id1 >> 2, c1 = id1 & 3;
    const uint32_t o0 = r0 * 64 + (((c0 ^ ((r0 >> 1) & 3))) << 4);
    const uint32_t o1 = r1 * 64 + (((c1 ^ ((r1 >> 1) & 3))) << 4);

    auto stage = [&](int k0, int s) {
        const uint32_t bb = smB + s * 32768;
        const size_t a0 = (size_t)(bm + r0) * 1024 + k0 + c0 * 8;
        const size_t a1 = (size_t)(bm + r1) * 1024 + k0 + c1 * 8;
        const size_t b0 = (size_t)(bn + r0) * 1024 + k0 + c0 * 8;
        const size_t b1 = (size_t)(bn + r1) * 1024 + k0 + c1 * 8;
        cpa16(bb + o0,         Ah + a0);  cpa16(bb + o1,         Ah + a1);
        if (p3) {
            cpa16(bb + 8192 + o0, Al + a0);
            cpa16(bb + 8192 + o1, Al + a1);
        }
        cpa16(bb + 16384 + o0, Bh + b0);  cpa16(bb + 16384 + o1, Bh + b1);
        cpa16(bb + 24576 + o0, Bl + b0);  cpa16(bb + 24576 + o1, Bl + b1);
        CP_COMMIT();
    };

    float c[4][4][4];
#pragma unroll
    for (int i = 0; i < 4; i++)
#pragma unroll
        for (int j = 0; j < 4; j++)
#pragma unroll
            for (int e = 0; e < 4; e++) c[i][j][e] = 0.f;

    stage(0, 0);
    stage(32, 1);

    for (int ki = 0; ki < 32; ki++) {
        if (ki < 31) asm volatile("cp.async.wait_group 1;" ::: "memory");
        else         asm volatile("cp.async.wait_group 0;" ::: "memory");
        __syncthreads();
        if (ki + 2 < 32) stage((ki + 2) * 32, (ki + 2) % 3);

        const uint32_t st = smB + (ki % 3) * 32768;

#pragma unroll
        for (int kk = 0; kk < 2; kk++) {
            uint32_t af[4][4];
#pragma unroll
            for (int i = 0; i < 4; i++) {
                const int row = wm * 64 + i * 16 + aRowF;
                ldm4(af[i], st + row * 64 +
                     (((2 * kk + aCh) ^ ((row >> 1) & 3)) << 4));
            }
            uint32_t bh4[2][4], bl4[2][4];
#pragma unroll
            for (int jp = 0; jp < 2; jp++) {
                const int row = wn * 32 + jp * 16 + bRowF;
                const uint32_t a = st + 16384 + row * 64 +
                                   (((2 * kk + bCh) ^ ((row >> 1) & 3)) << 4);
                ldm4(bh4[jp], a);
                ldm4(bl4[jp], a + 8192);
            }
#pragma unroll
            for (int jp = 0; jp < 2; jp++)
#pragma unroll
                for (int i = 0; i < 4; i++) {
                    mma16(c[i][2 * jp],     af[i], bh4[jp]);
                    mma16(c[i][2 * jp + 1], af[i], bh4[jp] + 2);
                }
#pragma unroll
            for (int jp = 0; jp < 2; jp++)
#pragma unroll
                for (int i = 0; i < 4; i++) {
                    mma16(c[i][2 * jp],     af[i], bl4[jp]);
                    mma16(c[i][2 * jp + 1], af[i], bl4[jp] + 2);
                }
            if (p3) {
#pragma unroll
                for (int i = 0; i < 4; i++) {
                    const int row = wm * 64 + i * 16 + aRowF;
                    ldm4(af[i], st + 8192 + row * 64 +
                         (((2 * kk + aCh) ^ ((row >> 1) & 3)) << 4));
                }
#pragma unroll
                for (int jp = 0; jp < 2; jp++)
#pragma unroll
                    for (int i = 0; i < 4; i++) {
                        mma16(c[i][2 * jp],     af[i], bh4[jp]);
                        mma16(c[i][2 * jp + 1], af[i], bh4[jp] + 2);
                    }
            }
        }
    }

#pragma unroll
    for (int i = 0; i < 4; i++) {
#pragma unroll
        for (int j = 0; j < 4; j++) {
            const int row = bm + wm * 64 + i * 16 + qr;
            const int col = bn + wn * 32 + j * 8 + 2 * qc;
            if (SPLIT) {
                const float sc = (QS && col < 1024) ? QSCALE : 1.f;
                uint32_t h0, l0, h1, l1;
                split2(c[i][j][0] * sc, c[i][j][1] * sc, h0, l0);
                split2(c[i][j][2] * sc, c[i][j][3] * sc, h1, l1);
                *(uint32_t*)(outH + (size_t)row * NOUT + col) = h0;
                *(uint32_t*)(outL + (size_t)row * NOUT + col) = l0;
                *(uint32_t*)(outH + (size_t)(row + 8) * NOUT + col) = h1;
                *(uint32_t*)(outL + (size_t)(row + 8) * NOUT + col) = l1;
            } else {
                *(float2*)(outF + (size_t)row * NOUT + col) =
                    make_float2(c[i][j][0], c[i][j][1]);
                *(float2*)(outF + (size_t)(row + 8) * NOUT + col) =
                    make_float2(c[i][j][2], c[i][j][3]);
            }
        }
    }
}

// ---------------------------------------------------------------------------
// Flash attention (causal) v5: LPT grid (bh fast, q-tile reversed on y),
// 3-stage KV pipeline, one barrier/tile, S 3-pass, PV = Ph*Vh, exp2 softmax.
// ---------------------------------------------------------------------------
#define FA_SMEM 73728

__global__ void __launch_bounds__(128, 3)
flash16(const __half* __restrict__ qh, const __half* __restrict__ ql,
        float* __restrict__ out)
{
    extern __shared__ char smx[];
    const uint32_t smB = su32(smx);
    const int tid  = threadIdx.x;
    const int w    = tid >> 5;
    const int lane = tid & 31;
    const int lr   = lane & 7, g = lane >> 3;
    const int qr   = lane >> 2, qc = lane & 3;
    const int bhx  = blockIdx.x;
    const int b    = bhx >> 4;
    const int hh   = bhx & 15;
    const int m0   = (gridDim.y - 1 - blockIdx.y) * 64;
    const int nt   = m0 / 64 + 1;

    const size_t base = (size_t)b * T_ * 3072 + hh * 64;
    const __half* qhp = qh + base;
    const __half* qlp = ql + base;
    const __half* khp = qhp + 1024;
    const __half* klp = qlp + 1024;
    const __half* vhp = qhp + 2048;

    int sRow[4], sC[4];
    uint32_t sDst[4];
#pragma unroll
    for (int q = 0; q < 4; q++) {
        int id = tid * 4 + q;
        sRow[q] = id >> 3;
        sC[q]   = id & 7;
        sDst[q] = sRow[q] * 128 + ((sC[q] ^ (sRow[q] & 7)) << 4);
    }

    auto stage_kv = [&](int t, int s) {
        const uint32_t bb = smB + s * 24576;
        const int j0 = t * 64;
#pragma unroll
        for (int q = 0; q < 4; q++) {
            const size_t so = (size_t)(j0 + sRow[q]) * 3072 + sC[q] * 8;
            cpa16(bb + sDst[q],         khp + so);
            cpa16(bb + 8192  + sDst[q], klp + so);
            cpa16(bb + 16384 + sDst[q], vhp + so);
        }
        CP_COMMIT();
    };

#pragma unroll
    for (int q = 0; q < 4; q++) {
        const size_t so = (size_t)(m0 + sRow[q]) * 3072 + sC[q] * 8;
        cpa16(smB + sDst[q],        qhp + so);
        cpa16(smB + 8192 + sDst[q], qlp + so);
    }
    CP_COMMIT();
    asm volatile("cp.async.wait_group 0;" ::: "memory");
    __syncthreads();

    const int aRow = lr + ((g & 1) << 3), aCh = g >> 1;
    const int kRow = lr + ((g >> 1) << 3), kCh = g & 1;
    uint32_t qfh[4][4], qfl[4][4];
#pragma unroll
    for (int kk = 0; kk < 4; kk++) {
        uint32_t a = smB + (w * 16 + aRow) * 128 + (((2 * kk + aCh) ^ lr) << 4);
        ldm4(qfh[kk], a);
        ldm4(qfl[kk], a + 8192);
    }
    __syncthreads();

    stage_kv(0, 0);
    if (nt > 1) stage_kv(1, 1);

    float o_[8][4];
#pragma unroll
    for (int n = 0; n < 8; n++)
#pragma unroll
        for (int e = 0; e < 4; e++) o_[n][e] = 0.f;
    float m0v = -1e30f, m1v = -1e30f, l0v = 0.f, l1v = 0.f;
    const int row0 = m0 + w * 16 + qr;

    for (int t = 0; t < nt; t++) {
        const int j0 = t * 64;
        if (t + 1 < nt) asm volatile("cp.async.wait_group 1;" ::: "memory");
        else            asm volatile("cp.async.wait_group 0;" ::: "memory");
        __syncthreads();
        if (t + 2 < nt) stage_kv(t + 2, (t + 2) % 3);

        const uint32_t KB = smB + (t % 3) * 24576;
        const uint32_t VB = KB + 16384;

        float s_[8][4];
#pragma unroll
        for (int n = 0; n < 8; n++)
#pragma unroll
            for (int e = 0; e < 4; e++) s_[n][e] = 0.f;

#pragma unroll
        for (int kk = 0; kk < 4; kk++) {
            uint32_t kh4[4][4], kl4[4][4];
#pragma unroll
            for (int np = 0; np < 4; np++) {
                uint32_t a = KB + np * 2048 + kRow * 128 +
                             (((2 * kk + kCh) ^ lr) << 4);
                ldm4(kh4[np], a);
                ldm4(kl4[np], a + 8192);
            }
#pragma unroll
            for (int np = 0; np < 4; np++) {
                mma16(s_[2 * np],     qfh[kk], kh4[np]);
                mma16(s_[2 * np + 1], qfh[kk], kh4[np] + 2);
            }
#pragma unroll
            for (int np = 0; np < 4; np++) {
                mma16(s_[2 * np],     qfh[kk], kl4[np]);
                mma16(s_[2 * np + 1], qfh[kk], kl4[np] + 2);
            }
#pragma unroll
            for (int np = 0; np < 4; np++) {
                mma16(s_[2 * np],     qfl[kk], kh4[np]);
                mma16(s_[2 * np + 1], qfl[kk], kh4[np] + 2);
            }
        }

        if (j0 == m0) {
#pragma unroll
            for (int n = 0; n < 8; n++) {
                const int key = j0 + n * 8 + 2 * qc;
                if (key     > row0)     s_[n][0] = -1e30f;
                if (key + 1 > row0)     s_[n][1] = -1e30f;
                if (key     > row0 + 8) s_[n][2] = -1e30f;
                if (key + 1 > row0 + 8) s_[n][3] = -1e30f;
            }
        }

        float mx0 = -1e30f, mx1 = -1e30f;
#pragma unroll
        for (int n = 0; n < 8; n++) {
            mx0 = fmaxf(mx0, fmaxf(s_[n][0], s_[n][1]));
            mx1 = fmaxf(mx1, fmaxf(s_[n][2], s_[n][3]));
        }
        mx0 = fmaxf(mx0, __shfl_xor_sync(0xffffffffu, mx0, 1));
        mx0 = fmaxf(mx0, __shfl_xor_sync(0xffffffffu, mx0, 2));
        mx1 = fmaxf(mx1, __shfl_xor_sync(0xffffffffu, mx1, 1));
        mx1 = fmaxf(mx1, __shfl_xor_sync(0xffffffffu, mx1, 2));
        const float mn0 = fmaxf(m0v, mx0);
        const float mn1 = fmaxf(m1v, mx1);
        const float c0 = exp2f(m0v - mn0);
        const float c1 = exp2f(m1v - mn1);
        m0v = mn0; m1v = mn1;
        l0v *= c0;  l1v *= c1;
#pragma unroll
        for (int n = 0; n < 8; n++) {
            o_[n][0] *= c0; o_[n][1] *= c0;
            o_[n][2] *= c1; o_[n][3] *= c1;
        }

        uint32_t pA[8], pB[8];
        float ps0 = 0.f, ps1 = 0.f;
#pragma unroll
        for (int n = 0; n < 8; n++) {
            float p0 = exp2f(s_[n][0] - mn0);
            float p1 = exp2f(s_[n][1] - mn0);
            float p2 = exp2f(s_[n][2] - mn1);
            float p3 = exp2f(s_[n][3] - mn1);
            ps0 += p0 + p1;
            ps1 += p2 + p3;
            pA[n] = pack_h2(p0, p1);
            pB[n] = pack_h2(p2, p3);
        }
        ps0 += __shfl_xor_sync(0xffffffffu, ps0, 1);
        ps0 += __shfl_xor_sync(0xffffffffu, ps0, 2);
        ps1 += __shfl_xor_sync(0xffffffffu, ps1, 1);
        ps1 += __shfl_xor_sync(0xffffffffu, ps1, 2);
        l0v += ps0; l1v += ps1;

#pragma unroll
        for (int kk = 0; kk < 4; kk++) {
            uint32_t ah4[4] = { pA[2 * kk], pB[2 * kk],
                                pA[2 * kk + 1], pB[2 * kk + 1] };
#pragma unroll
            for (int np = 0; np < 4; np++) {
                uint32_t vh4[4];
                uint32_t a = VB + kk * 2048 + aRow * 128 +
                             (((2 * np + aCh) ^ lr) << 4);
                ldm4t(vh4, a);
                mma16(o_[2 * np],     ah4, vh4);
                mma16(o_[2 * np + 1], ah4, vh4 + 2);
            }
        }
    }

    const float i0 = 1.f / l0v;
    const float i1 = 1.f / l1v;
    float* oP0 = out + ((size_t)b * T_ + row0) * C_ + hh * 64;
    float* oP1 = oP0 + 8 * C_;
#pragma unroll
    for (int n = 0; n < 8; n++) {
        *(float2*)(oP0 + n * 8 + 2 * qc) = make_float2(o_[n][0] * i0, o_[n][1] * i0);
        *(float2*)(oP1 + n * 8 + 2 * qc) = make_float2(o_[n][2] * i1, o_[n][3] * i1);
    }
}

// ---------------------------------------------------------------------------
// Depthwise causal conv (K=4) + bias + residual -> fp16 hi only
// ---------------------------------------------------------------------------
__global__ void __launch_bounds__(256)
conv_h(const float* __restrict__ x, const float* __restrict__ w,
       const float* __restrict__ bias, __half* __restrict__ yh)
{
    int i2 = blockIdx.x * blockDim.x + threadIdx.x;
    if (i2 >= MTOK * C_ / 2) return;
    const int idx = i2 * 2;
    const int c = idx & (C_ - 1);
    const int t = (idx >> 10) & (T_ - 1);

    float s0 = bias[c]     + x[idx];
    float s1 = bias[c + 1] + x[idx + 1];
#pragma unroll
    for (int k = 0; k < 4; k++) {
        int ts = t + k - 3;
        if (ts >= 0) {
            s0 += w[c * 4 + k]       * x[idx + (k - 3) * C_];
            s1 += w[(c + 1) * 4 + k] * x[idx + 1 + (k - 3) * C_];
        }
    }
    *(uint32_t*)(yh + idx) = pack_h2(s0, s1);
}

// ---------------------------------------------------------------------------
// Launch
// ---------------------------------------------------------------------------
extern "C" void kernel_launch(void* const* d_in, const int* in_sizes, int n_in,
                              void* d_out, int out_size)
{
    const float* x     = (const float*)d_in[0];
    const float* Wqkv  = (const float*)d_in[1];
    const float* Wout  = (const float*)d_in[2];
    const float* convw = (const float*)d_in[3];
    const float* convb = (const float*)d_in[4];
    float* out = (float*)d_out;

    __half *xh, *xl, *wqh, *wql, *woh, *wol, *qh, *ql, *ch;
    float* attn;
    cudaGetSymbolAddress((void**)&xh,  g_xh);
    cudaGetSymbolAddress((void**)&xl,  g_xl);
    cudaGetSymbolAddress((void**)&wqh, g_wqh);
    cudaGetSymbolAddress((void**)&wql, g_wql);
    cudaGetSymbolAddress((void**)&woh, g_woh);
    cudaGetSymbolAddress((void**)&wol, g_wol);
    cudaGetSymbolAddress((void**)&qh,  g_qh);
    cudaGetSymbolAddress((void**)&ql,  g_ql);
    cudaGetSymbolAddress((void**)&ch,  g_ch);
    cudaGetSymbolAddress((void**)&attn, g_attn);

    cudaFuncSetAttribute((const void*)gemm16<3072, true, 0, true>,
                         cudaFuncAttributeMaxDynamicSharedMemorySize, GSM);
    cudaFuncSetAttribute((const void*)gemm16<1024, false, 2, false>,
                         cudaFuncAttributeMaxDynamicSharedMemorySize, GSM);
    cudaFuncSetAttribute((const void*)flash16,
                         cudaFuncAttributeMaxDynamicSharedMemorySize, FA_SMEM);

    // 0) fused splits: x, Wqkv, Wout in one launch
    const int nsplit = X2 + WQ2 + WO2;
    split_all<<<(nsplit + 255) / 256, 256>>>(
        (const float2*)x, (const float2*)Wqkv, (const float2*)Wout,
        (__half2*)xh, (__half2*)xl, (__half2*)wqh, (__half2*)wql,
        (__half2*)woh, (__half2*)wol);

    // 1) QKV projection, single launch: Q+K CTAs 3-pass (Q cols scaled),
    //    V CTAs (bn>=2048) 2-pass — wave-packed together.
    gemm16<3072, true, 0, true><<<dim3(24, 64), 256, GSM>>>(
        xh, xl, wqh, wql, nullptr, qh, ql);

    // 2) attention — LPT grid
    flash16<<<dim3(B_ * H_, T_ / 64), 128, FA_SMEM>>>(qh, ql, attn);

    // 3) conv + residual -> fp16 hi
    conv_h<<<MTOK * C_ / 2 / 256, 256>>>(attn, convw, convb, ch);

    // 4) output projection: 2-pass
    gemm16<1024, false, 2, false><<<dim3(8, 64), 256, GSM>>>(
        ch, nullptr, woh, wol, out, nullptr, nullptr);
}

// round 17
// speedup vs baseline: 1.0513x; 1.0314x over previous
#include <cuda_runtime.h>
#include <cuda_fp16.h>
#include <cstdint>
#include <cstddef>

#define B_   4
#define T_   2048
#define C_   1024
#define H_   16
#define MTOK 8192
// Q scale folded with log2(e) for exp2-domain softmax
#define QSCALE 0.18033688011112042f

// ---------------------------------------------------------------------------
// Scratch
// ---------------------------------------------------------------------------
__device__ __half g_xh[(size_t)MTOK * C_],     g_xl[(size_t)MTOK * C_];
__device__ __half g_wqh[(size_t)3 * C_ * C_],  g_wql[(size_t)3 * C_ * C_];
__device__ __half g_woh[(size_t)C_ * C_],      g_wol[(size_t)C_ * C_];
__device__ __half g_qh[(size_t)MTOK * 3 * C_], g_ql[(size_t)MTOK * 3 * C_];
__device__ __half g_ch[(size_t)MTOK * C_];
__device__ float  g_attn[(size_t)MTOK * C_];

// ---------------------------------------------------------------------------
// Helpers
// ---------------------------------------------------------------------------
__device__ __forceinline__ uint32_t su32(const void* p) {
    uint32_t a;
    asm("{ .reg .u64 t; cvta.to.shared.u64 t, %1; cvt.u32.u64 %0, t; }"
        : "=r"(a) : "l"(p));
    return a;
}
__device__ __forceinline__ void cpa16(uint32_t dst, const void* src) {
    asm volatile("cp.async.cg.shared.global [%0], [%1], 16;" :: "r"(dst), "l"(src));
}
#define CP_COMMIT() asm volatile("cp.async.commit_group;" ::: "memory")

__device__ __forceinline__ void ldm4(uint32_t* r, uint32_t a) {
    asm volatile("ldmatrix.sync.aligned.m8n8.x4.shared.b16 {%0,%1,%2,%3}, [%4];"
                 : "=r"(r[0]), "=r"(r[1]), "=r"(r[2]), "=r"(r[3]) : "r"(a));
}
__device__ __forceinline__ void ldm4t(uint32_t* r, uint32_t a) {
    asm volatile("ldmatrix.sync.aligned.m8n8.x4.trans.shared.b16 {%0,%1,%2,%3}, [%4];"
                 : "=r"(r[0]), "=r"(r[1]), "=r"(r[2]), "=r"(r[3]) : "r"(a));
}
__device__ __forceinline__ void mma16(float* d, const uint32_t* a, const uint32_t* b) {
    asm volatile(
        "mma.sync.aligned.m16n8k16.row.col.f32.f16.f16.f32 "
        "{%0,%1,%2,%3}, {%4,%5,%6,%7}, {%8,%9}, {%0,%1,%2,%3};"
        : "+f"(d[0]), "+f"(d[1]), "+f"(d[2]), "+f"(d[3])
        : "r"(a[0]), "r"(a[1]), "r"(a[2]), "r"(a[3]), "r"(b[0]), "r"(b[1]));
}
__device__ __forceinline__ void split2(float x, float y, uint32_t& h, uint32_t& l) {
    __half2 hh = __float22half2_rn(make_float2(x, y));
    float rx = x - __half2float(__low2half(hh));
    float ry = y - __half2float(__high2half(hh));
    __half2 ll = __float22half2_rn(make_float2(rx, ry));
    h = *reinterpret_cast<uint32_t*>(&hh);
    l = *reinterpret_cast<uint32_t*>(&ll);
}
__device__ __forceinline__ uint32_t pack_h2(float x, float y) {
    __half2 hh = __float22half2_rn(make_float2(x, y));
    return *reinterpret_cast<uint32_t*>(&hh);
}

// ---------------------------------------------------------------------------
// Fused fp32 -> fp16 hi/lo split (x, Wqkv, Wout in one launch)
// ---------------------------------------------------------------------------
#define X2  (MTOK * C_ / 2)
#define WQ2 (3 * C_ * C_ / 2)
#define WO2 (C_ * C_ / 2)

__global__ void __launch_bounds__(256)
split_all(const float2* __restrict__ x, const float2* __restrict__ wq,
          const float2* __restrict__ wo,
          __half2* __restrict__ xh, __half2* __restrict__ xl,
          __half2* __restrict__ wqh, __half2* __restrict__ wql,
          __half2* __restrict__ woh, __half2* __restrict__ wol)
{
    int i = blockIdx.x * blockDim.x + threadIdx.x;
    const float2* src;
    __half2 *dh, *dl;
    if (i < X2)                  { src = x  + i;               dh = xh  + i;               dl = xl  + i; }
    else if (i < X2 + WQ2)       { src = wq + (i - X2);        dh = wqh + (i - X2);        dl = wql + (i - X2); }
    else if (i < X2 + WQ2 + WO2) { src = wo + (i - X2 - WQ2);  dh = woh + (i - X2 - WQ2);  dl = wol + (i - X2 - WQ2); }
    else return;
    float2 v = *src;
    uint32_t h, l;
    split2(v.x, v.y, h, l);
    *dh = *reinterpret_cast<__half2*>(&h);
    *dl = *reinterpret_cast<__half2*>(&l);
}

// ---------------------------------------------------------------------------
// fp16-compensated GEMM (NT): 128x128 tile, BK=32, 3-stage pipeline,
// one __syncthreads per chunk, 2 CTAs/SM.
// NPASS=3: hh+hl+lh.  NPASS=2: hh+hl.
// NPASS=0 (MIXED, QKV): bn<2048 -> 3-pass (+QSCALE on cols<1024), else 2-pass.
// ---------------------------------------------------------------------------
#define GSM 98304

template<int NOUT, bool SPLIT, int NPASS, bool QS>
__global__ void __launch_bounds__(256, 2)
gemm16(const __half* __restrict__ Ah, const __half* __restrict__ Al,
       const __half* __restrict__ Bh, const __half* __restrict__ Bl,
       float* __restrict__ outF, __half* __restrict__ outH,
       __half* __restrict__ outL)
{
    extern __shared__ char smx[];
    const uint32_t smB = su32(smx);
    const int tid  = threadIdx.x;
    const int lane = tid & 31;
    const int wid  = tid >> 5;
    const int wm   = wid & 1;
    const int wn   = wid >> 1;
    const int lr   = lane & 7, g = lane >> 3;
    const int qr   = lane >> 2, qc = lane & 3;
    const int bm   = blockIdx.y * 128;
    const int bn   = blockIdx.x * 128;

    const bool p3 = (NPASS == 3) || (NPASS == 0 && bn < 2048);

    const int aCh = g >> 1;
    const int bCh = g & 1;
    const int aRowF = lr + ((g & 1) << 3);
    const int bRowF = lr + ((g >> 1) << 3);

    const int id0 = tid * 2, id1 = tid * 2 + 1;
    const int r0 = id0 >> 2, c0 = id0 & 3;
    const int r1 = id1 >> 2, c1 = id1 & 3;
    const uint32_t o0 = r0 * 64 + (((c0 ^ ((r0 >> 1) & 3))) << 4);
    const uint32_t o1 = r1 * 64 + (((c1 ^ ((r1 >> 1) & 3))) << 4);

    auto stage = [&](int k0, int s) {
        const uint32_t bb = smB + s * 32768;
        const size_t a0 = (size_t)(bm + r0) * 1024 + k0 + c0 * 8;
        const size_t a1 = (size_t)(bm + r1) * 1024 + k0 + c1 * 8;
        const size_t b0 = (size_t)(bn + r0) * 1024 + k0 + c0 * 8;
        const size_t b1 = (size_t)(bn + r1) * 1024 + k0 + c1 * 8;
        cpa16(bb + o0,         Ah + a0);  cpa16(bb + o1,         Ah + a1);
        if (p3) {
            cpa16(bb + 8192 + o0, Al + a0);
            cpa16(bb + 8192 + o1, Al + a1);
        }
        cpa16(bb + 16384 + o0, Bh + b0);  cpa16(bb + 16384 + o1, Bh + b1);
        cpa16(bb + 24576 + o0, Bl + b0);  cpa16(bb + 24576 + o1, Bl + b1);
        CP_COMMIT();
    };

    float c[4][4][4];
#pragma unroll
    for (int i = 0; i < 4; i++)
#pragma unroll
        for (int j = 0; j < 4; j++)
#pragma unroll
            for (int e = 0; e < 4; e++) c[i][j][e] = 0.f;

    stage(0, 0);
    stage(32, 1);

    for (int ki = 0; ki < 32; ki++) {
        if (ki < 31) asm volatile("cp.async.wait_group 1;" ::: "memory");
        else         asm volatile("cp.async.wait_group 0;" ::: "memory");
        __syncthreads();
        if (ki + 2 < 32) stage((ki + 2) * 32, (ki + 2) % 3);

        const uint32_t st = smB + (ki % 3) * 32768;

#pragma unroll
        for (int kk = 0; kk < 2; kk++) {
            uint32_t af[4][4];
#pragma unroll
            for (int i = 0; i < 4; i++) {
                const int row = wm * 64 + i * 16 + aRowF;
                ldm4(af[i], st + row * 64 +
                     (((2 * kk + aCh) ^ ((row >> 1) & 3)) << 4));
            }
            uint32_t bh4[2][4], bl4[2][4];
#pragma unroll
            for (int jp = 0; jp < 2; jp++) {
                const int row = wn * 32 + jp * 16 + bRowF;
                const uint32_t a = st + 16384 + row * 64 +
                                   (((2 * kk + bCh) ^ ((row >> 1) & 3)) << 4);
                ldm4(bh4[jp], a);
                ldm4(bl4[jp], a + 8192);
            }
#pragma unroll
            for (int jp = 0; jp < 2; jp++)
#pragma unroll
                for (int i = 0; i < 4; i++) {
                    mma16(c[i][2 * jp],     af[i], bh4[jp]);
                    mma16(c[i][2 * jp + 1], af[i], bh4[jp] + 2);
                }
#pragma unroll
            for (int jp = 0; jp < 2; jp++)
#pragma unroll
                for (int i = 0; i < 4; i++) {
                    mma16(c[i][2 * jp],     af[i], bl4[jp]);
                    mma16(c[i][2 * jp + 1], af[i], bl4[jp] + 2);
                }
            if (p3) {
#pragma unroll
                for (int i = 0; i < 4; i++) {
                    const int row = wm * 64 + i * 16 + aRowF;
                    ldm4(af[i], st + 8192 + row * 64 +
                         (((2 * kk + aCh) ^ ((row >> 1) & 3)) << 4));
                }
#pragma unroll
                for (int jp = 0; jp < 2; jp++)
#pragma unroll
                    for (int i = 0; i < 4; i++) {
                        mma16(c[i][2 * jp],     af[i], bh4[jp]);
                        mma16(c[i][2 * jp + 1], af[i], bh4[jp] + 2);
                    }
            }
        }
    }

#pragma unroll
    for (int i = 0; i < 4; i++) {
#pragma unroll
        for (int j = 0; j < 4; j++) {
            const int row = bm + wm * 64 + i * 16 + qr;
            const int col = bn + wn * 32 + j * 8 + 2 * qc;
            if (SPLIT) {
                const float sc = (QS && col < 1024) ? QSCALE : 1.f;
                uint32_t h0, l0, h1, l1;
                split2(c[i][j][0] * sc, c[i][j][1] * sc, h0, l0);
                split2(c[i][j][2] * sc, c[i][j][3] * sc, h1, l1);
                *(uint32_t*)(outH + (size_t)row * NOUT + col) = h0;
                *(uint32_t*)(outL + (size_t)row * NOUT + col) = l0;
                *(uint32_t*)(outH + (size_t)(row + 8) * NOUT + col) = h1;
                *(uint32_t*)(outL + (size_t)(row + 8) * NOUT + col) = l1;
            } else {
                *(float2*)(outF + (size_t)row * NOUT + col) =
                    make_float2(c[i][j][0], c[i][j][1]);
                *(float2*)(outF + (size_t)(row + 8) * NOUT + col) =
                    make_float2(c[i][j][2], c[i][j][3]);
            }
        }
    }
}

// ---------------------------------------------------------------------------
// Flash attention (causal) v6: 128-query tile, 256 threads (8 warps x 16
// rows) — halves KV staging traffic (L2-bound component). LPT grid, 3-stage
// KV pipeline (24KB/stage), one barrier/tile, S 3-pass, PV = Ph*Vh, exp2
// softmax. Q staged to 32KB (hi, lo at +16KB) then recycled. 72KB, 2 CTAs/SM.
// ---------------------------------------------------------------------------
#define FA_SMEM 73728

__global__ void __launch_bounds__(256, 2)
flash16(const __half* __restrict__ qh, const __half* __restrict__ ql,
        float* __restrict__ out)
{
    extern __shared__ char smx[];
    const uint32_t smB = su32(smx);
    const int tid  = threadIdx.x;
    const int w    = tid >> 5;             // 0..7
    const int lane = tid & 31;
    const int lr   = lane & 7, g = lane >> 3;
    const int qr   = lane >> 2, qc = lane & 3;
    const int bhx  = blockIdx.x;
    const int b    = bhx >> 4;
    const int hh   = bhx & 15;
    const int m0   = (gridDim.y - 1 - blockIdx.y) * 128;  // LPT: largest first
    const int nt   = m0 / 64 + 2;          // KV tiles (64 keys each)

    const size_t base = (size_t)b * T_ * 3072 + hh * 64;
    const __half* qhp = qh + base;
    const __half* qlp = ql + base;
    const __half* khp = qhp + 1024;
    const __half* klp = qlp + 1024;
    const __half* vhp = qhp + 2048;

    // KV staging map: 512 chunks over 256 threads = 2 each
    int kRow_[2], kC_[2];
    uint32_t kDst[2];
#pragma unroll
    for (int q = 0; q < 2; q++) {
        int id = tid * 2 + q;
        kRow_[q] = id >> 3;
        kC_[q]   = id & 7;
        kDst[q]  = kRow_[q] * 128 + ((kC_[q] ^ (kRow_[q] & 7)) << 4);
    }
    // Q staging map: 1024 chunks over 256 threads = 4 each (128 rows)
    int qRow_[4], qC_[4];
    uint32_t qDst[4];
#pragma unroll
    for (int q = 0; q < 4; q++) {
        int id = tid * 4 + q;
        qRow_[q] = id >> 3;
        qC_[q]   = id & 7;
        qDst[q]  = qRow_[q] * 128 + ((qC_[q] ^ (qRow_[q] & 7)) << 4);
    }

    auto stage_kv = [&](int t, int s) {
        const uint32_t bb = smB + s * 24576;
        const int j0 = t * 64;
#pragma unroll
        for (int q = 0; q < 2; q++) {
            const size_t so = (size_t)(j0 + kRow_[q]) * 3072 + kC_[q] * 8;
            cpa16(bb + kDst[q],         khp + so);
            cpa16(bb + 8192  + kDst[q], klp + so);
            cpa16(bb + 16384 + kDst[q], vhp + so);
        }
        CP_COMMIT();
    };

    // stage Q (128 rows): hi at [0,16K), lo at [16K,32K); recycled afterwards
#pragma unroll
    for (int q = 0; q < 4; q++) {
        const size_t so = (size_t)(m0 + qRow_[q]) * 3072 + qC_[q] * 8;
        cpa16(smB + qDst[q],         qhp + so);
        cpa16(smB + 16384 + qDst[q], qlp + so);
    }
    CP_COMMIT();
    asm volatile("cp.async.wait_group 0;" ::: "memory");
    __syncthreads();

    const int aRow = lr + ((g & 1) << 3), aCh = g >> 1;
    const int kRowF = lr + ((g >> 1) << 3), kCh = g & 1;
    uint32_t qfh[4][4], qfl[4][4];
#pragma unroll
    for (int kk = 0; kk < 4; kk++) {
        uint32_t a = smB + (w * 16 + aRow) * 128 + (((2 * kk + aCh) ^ lr) << 4);
        ldm4(qfh[kk], a);
        ldm4(qfl[kk], a + 16384);
    }
    __syncthreads();          // Q fragments in regs before staging overwrites

    stage_kv(0, 0);
    stage_kv(1, 1);           // nt >= 2 always

    float o_[8][4];
#pragma unroll
    for (int n = 0; n < 8; n++)
#pragma unroll
        for (int e = 0; e < 4; e++) o_[n][e] = 0.f;
    float m0v = -1e30f, m1v = -1e30f, l0v = 0.f, l1v = 0.f;
    const int row0 = m0 + w * 16 + qr;

    for (int t = 0; t < nt; t++) {
        const int j0 = t * 64;
        if (t + 1 < nt) asm volatile("cp.async.wait_group 1;" ::: "memory");
        else            asm volatile("cp.async.wait_group 0;" ::: "memory");
        __syncthreads();
        if (t + 2 < nt) stage_kv(t + 2, (t + 2) % 3);

        const uint32_t KB = smB + (t % 3) * 24576;
        const uint32_t VB = KB + 16384;

        float s_[8][4];
#pragma unroll
        for (int n = 0; n < 8; n++)
#pragma unroll
            for (int e = 0; e < 4; e++) s_[n][e] = 0.f;

        // ---- S = Q K^T (3-pass compensated) ----
#pragma unroll
        for (int kk = 0; kk < 4; kk++) {
            uint32_t kh4[4][4], kl4[4][4];
#pragma unroll
            for (int np = 0; np < 4; np++) {
                uint32_t a = KB + np * 2048 + kRowF * 128 +
                             (((2 * kk + kCh) ^ lr) << 4);
                ldm4(kh4[np], a);
                ldm4(kl4[np], a + 8192);
            }
#pragma unroll
            for (int np = 0; np < 4; np++) {
                mma16(s_[2 * np],     qfh[kk], kh4[np]);
                mma16(s_[2 * np + 1], qfh[kk], kh4[np] + 2);
            }
#pragma unroll
            for (int np = 0; np < 4; np++) {
                mma16(s_[2 * np],     qfh[kk], kl4[np]);
                mma16(s_[2 * np + 1], qfh[kk], kl4[np] + 2);
            }
#pragma unroll
            for (int np = 0; np < 4; np++) {
                mma16(s_[2 * np],     qfl[kk], kh4[np]);
                mma16(s_[2 * np + 1], qfl[kk], kh4[np] + 2);
            }
        }

        // ---- causal mask (last two tiles overlap the diagonal) ----
        if (j0 + 64 > m0) {
#pragma unroll
            for (int n = 0; n < 8; n++) {
                const int key = j0 + n * 8 + 2 * qc;
                if (key     > row0)     s_[n][0] = -1e30f;
                if (key + 1 > row0)     s_[n][1] = -1e30f;
                if (key     > row0 + 8) s_[n][2] = -1e30f;
                if (key + 1 > row0 + 8) s_[n][3] = -1e30f;
            }
        }

        // ---- online softmax (exp2 domain) ----
        float mx0 = -1e30f, mx1 = -1e30f;
#pragma unroll
        for (int n = 0; n < 8; n++) {
            mx0 = fmaxf(mx0, fmaxf(s_[n][0], s_[n][1]));
            mx1 = fmaxf(mx1, fmaxf(s_[n][2], s_[n][3]));
        }
        mx0 = fmaxf(mx0, __shfl_xor_sync(0xffffffffu, mx0, 1));
        mx0 = fmaxf(mx0, __shfl_xor_sync(0xffffffffu, mx0, 2));
        mx1 = fmaxf(mx1, __shfl_xor_sync(0xffffffffu, mx1, 1));
        mx1 = fmaxf(mx1, __shfl_xor_sync(0xffffffffu, mx1, 2));
        const float mn0 = fmaxf(m0v, mx0);
        const float mn1 = fmaxf(m1v, mx1);
        const float c0 = exp2f(m0v - mn0);
        const float c1 = exp2f(m1v - mn1);
        m0v = mn0; m1v = mn1;
        l0v *= c0;  l1v *= c1;
#pragma unroll
        for (int n = 0; n < 8; n++) {
            o_[n][0] *= c0; o_[n][1] *= c0;
            o_[n][2] *= c1; o_[n][3] *= c1;
        }

        uint32_t pA[8], pB[8];
        float ps0 = 0.f, ps1 = 0.f;
#pragma unroll
        for (int n = 0; n < 8; n++) {
            float p0 = exp2f(s_[n][0] - mn0);
            float p1 = exp2f(s_[n][1] - mn0);
            float p2 = exp2f(s_[n][2] - mn1);
            float p3 = exp2f(s_[n][3] - mn1);
            ps0 += p0 + p1;
            ps1 += p2 + p3;
            pA[n] = pack_h2(p0, p1);
            pB[n] = pack_h2(p2, p3);
        }
        ps0 += __shfl_xor_sync(0xffffffffu, ps0, 1);
        ps0 += __shfl_xor_sync(0xffffffffu, ps0, 2);
        ps1 += __shfl_xor_sync(0xffffffffu, ps1, 1);
        ps1 += __shfl_xor_sync(0xffffffffu, ps1, 2);
        l0v += ps0; l1v += ps1;

        // ---- O += Ph * Vh ----
#pragma unroll
        for (int kk = 0; kk < 4; kk++) {
            uint32_t ah4[4] = { pA[2 * kk], pB[2 * kk],
                                pA[2 * kk + 1], pB[2 * kk + 1] };
#pragma unroll
            for (int np = 0; np < 4; np++) {
                uint32_t vh4[4];
                uint32_t a = VB + kk * 2048 + aRow * 128 +
                             (((2 * np + aCh) ^ lr) << 4);
                ldm4t(vh4, a);
                mma16(o_[2 * np],     ah4, vh4);
                mma16(o_[2 * np + 1], ah4, vh4 + 2);
            }
        }
    }

    const float i0 = 1.f / l0v;
    const float i1 = 1.f / l1v;
    float* oP0 = out + ((size_t)b * T_ + row0) * C_ + hh * 64;
    float* oP1 = oP0 + 8 * C_;
#pragma unroll
    for (int n = 0; n < 8; n++) {
        *(float2*)(oP0 + n * 8 + 2 * qc) = make_float2(o_[n][0] * i0, o_[n][1] * i0);
        *(float2*)(oP1 + n * 8 + 2 * qc) = make_float2(o_[n][2] * i1, o_[n][3] * i1);
    }
}

// ---------------------------------------------------------------------------
// Depthwise causal conv (K=4) + bias + residual -> fp16 hi, x4 vectorized
// ---------------------------------------------------------------------------
__global__ void __launch_bounds__(256)
conv_h(const float* __restrict__ x, const float* __restrict__ w,
       const float* __restrict__ bias, __half* __restrict__ yh)
{
    int i4 = blockIdx.x * blockDim.x + threadIdx.x;
    if (i4 >= MTOK * C_ / 4) return;
    const int idx = i4 * 4;
    const int c = idx & (C_ - 1);
    const int t = (idx >> 10) & (T_ - 1);

    float4 xv = *(const float4*)(x + idx);
    float4 bv = *(const float4*)(bias + c);
    float s[4] = { bv.x + xv.x, bv.y + xv.y, bv.z + xv.z, bv.w + xv.w };
    float4 tw[4];
#pragma unroll
    for (int q = 0; q < 4; q++) tw[q] = *(const float4*)(w + (c + q) * 4);

#pragma unroll
    for (int k = 0; k < 4; k++) {
        const int ts = t + k - 3;
        if (ts >= 0) {
            float4 xk = *(const float4*)(x + idx + (k - 3) * C_);
            s[0] += ((const float*)&tw[0])[k] * xk.x;
            s[1] += ((const float*)&tw[1])[k] * xk.y;
            s[2] += ((const float*)&tw[2])[k] * xk.z;
            s[3] += ((const float*)&tw[3])[k] * xk.w;
        }
    }
    uint2 o;
    o.x = pack_h2(s[0], s[1]);
    o.y = pack_h2(s[2], s[3]);
    *(uint2*)(yh + idx) = o;
}

// ---------------------------------------------------------------------------
// Launch
// ---------------------------------------------------------------------------
extern "C" void kernel_launch(void* const* d_in, const int* in_sizes, int n_in,
                              void* d_out, int out_size)
{
    const float* x     = (const float*)d_in[0];
    const float* Wqkv  = (const float*)d_in[1];
    const float* Wout  = (const float*)d_in[2];
    const float* convw = (const float*)d_in[3];
    const float* convb = (const float*)d_in[4];
    float* out = (float*)d_out;

    __half *xh, *xl, *wqh, *wql, *woh, *wol, *qh, *ql, *ch;
    float* attn;
    cudaGetSymbolAddress((void**)&xh,  g_xh);
    cudaGetSymbolAddress((void**)&xl,  g_xl);
    cudaGetSymbolAddress((void**)&wqh, g_wqh);
    cudaGetSymbolAddress((void**)&wql, g_wql);
    cudaGetSymbolAddress((void**)&woh, g_woh);
    cudaGetSymbolAddress((void**)&wol, g_wol);
    cudaGetSymbolAddress((void**)&qh,  g_qh);
    cudaGetSymbolAddress((void**)&ql,  g_ql);
    cudaGetSymbolAddress((void**)&ch,  g_ch);
    cudaGetSymbolAddress((void**)&attn, g_attn);

    cudaFuncSetAttribute((const void*)gemm16<3072, true, 0, true>,
                         cudaFuncAttributeMaxDynamicSharedMemorySize, GSM);
    cudaFuncSetAttribute((const void*)gemm16<1024, false, 2, false>,
                         cudaFuncAttributeMaxDynamicSharedMemorySize, GSM);
    cudaFuncSetAttribute((const void*)flash16,
                         cudaFuncAttributeMaxDynamicSharedMemorySize, FA_SMEM);

    // 0) fused splits
    const int nsplit = X2 + WQ2 + WO2;
    split_all<<<(nsplit + 255) / 256, 256>>>(
        (const float2*)x, (const float2*)Wqkv, (const float2*)Wout,
        (__half2*)xh, (__half2*)xl, (__half2*)wqh, (__half2*)wql,
        (__half2*)woh, (__half2*)wol);

    // 1) QKV projection, single wave-packed launch (QK 3-pass, V 2-pass)
    gemm16<3072, true, 0, true><<<dim3(24, 64), 256, GSM>>>(
        xh, xl, wqh, wql, nullptr, qh, ql);

    // 2) attention — 128-query tiles, LPT grid
    flash16<<<dim3(B_ * H_, T_ / 128), 256, FA_SMEM>>>(qh, ql, attn);

    // 3) conv + residual -> fp16 hi (x4 vectorized)
    conv_h<<<MTOK * C_ / 4 / 256, 256>>>(attn, convw, convb, ch);

    // 4) output projection: 2-pass
    gemm16<1024, false, 2, false><<<dim3(8, 64), 256, GSM>>>(
        ch, nullptr, woh, wol, out, nullptr, nullptr);
}